// round 8
// baseline (speedup 1.0000x reference)
#include <cuda_runtime.h>
#include <math.h>
#include <stdint.h>

#define SMAX 2048
#define WDIM 1024

// ---------------- scratch (static device globals; no allocation) -------------
__device__ float g_H1[SMAX * WDIM];     // 8 MB
__device__ float g_H2[SMAX * WDIM];     // 8 MB
__device__ float g_W2r[WDIM * WDIM];    // 4 MB (RNA tf32-rounded W2)
__device__ float g_W3r[WDIM * WDIM];    // 4 MB (RNA tf32-rounded W3)
__device__ float g_HSUM[WDIM];
__device__ float g_M[64 * 64];
__device__ float g_bsum;

__device__ __forceinline__ float gelu_f(float x) {
    float t = tanhf(0.7978845608028654f * (x + 0.044715f * x * x * x));
    return 0.5f * x * (1.0f + t);
}

__device__ __forceinline__ float tf32r(float x) {
    uint32_t u;
    asm("cvt.rna.tf32.f32 %0, %1;" : "=r"(u) : "f"(x));
    return __uint_as_float(u);
}

__device__ __forceinline__ void cp_async16(uint32_t dst, const void* src) {
    asm volatile("cp.async.cg.shared.global [%0], [%1], 16;\n" :: "r"(dst), "l"(src));
}

__device__ __forceinline__ unsigned long long pk2(float a, float b) {
    unsigned long long d;
    asm("mov.b64 %0, {%1, %2};" : "=l"(d) : "f"(a), "f"(b));
    return d;
}
__device__ __forceinline__ void fma2(unsigned long long& d, unsigned long long a,
                                     unsigned long long b) {
    asm("fma.rn.f32x2 %0, %1, %2, %0;" : "+l"(d) : "l"(a), "l"(b));
}

// ---------- fused prep: W2/W3 RNA rounding | layer1 | bsum + hsum-zero ------
__global__ void k_prep(const float* __restrict__ src, const float* __restrict__ W1,
                       const float* __restrict__ b1, const float* __restrict__ W2,
                       const float* __restrict__ W3, const float* __restrict__ Wb,
                       const float* __restrict__ bb, int S) {
    int bid = blockIdx.x;
    int tid = threadIdx.x;
    if (bid < 4096) {                       // RNA-round weights: 2 x 1M elems
        int i = bid * 256 + tid;
        g_W2r[i] = tf32r(W2[i]);
        g_W3r[i] = tf32r(W3[i]);
    } else if (bid < 12288) {               // layer 1: 2M outputs
        int idx = (bid - 4096) * 256 + tid;
        int s = idx >> 10, o = idx & (WDIM - 1);
        float4 w  = *(const float4*)(W1 + 4 * o);
        float4 sv = *(const float4*)(src + 4 * s);
        float v = b1[o] + sv.x * w.x + sv.y * w.y + sv.z * w.z + sv.w * w.w;
        g_H1[idx] = tf32r(gelu_f(v));
    } else {                                // bias reduce + zero HSUM
        __shared__ float red[256];
        *(float4*)(g_HSUM + tid * 4) = make_float4(0.f, 0.f, 0.f, 0.f);
        float w0 = Wb[0], w1 = Wb[1], w2 = Wb[2], w3 = Wb[3];
        float acc = 0.f;
        for (int s = tid; s < S; s += 256) {
            float4 sv = *(const float4*)(src + 4 * s);
            acc += sv.x * w0 + sv.y * w1 + sv.z * w2 + sv.w * w3;
        }
        red[tid] = acc;
        __syncthreads();
        for (int off = 128; off > 0; off >>= 1) {
            if (tid < off) red[tid] += red[tid + off];
            __syncthreads();
        }
        if (tid == 0) g_bsum = red[0] + (float)S * bb[0];
    }
}

// ---------------- tf32 tensor-core GEMM: C = gelu(A @ B^T + bias) -----------
// CTA tile 64x64, 128 threads = 4 warps (2x2), warp tile 32x32.
// 3-stage cp.async, BK=16, grid (16,32) = 512 CTAs -> 5-6 CTAs/SM resident.
// Both operands RNA tf32-rounded (device-global B selected via template —
// device symbols must NOT be passed as host-side kernel args).
// SRC==1: A=g_H1, B=g_W2r -> store tf32(gelu) to g_H2.
// SRC==2: A=g_H2, B=g_W3r -> fused column-sum of gelu into g_HSUM (atomics).
#define GP 20   // smem pitch in floats

__device__ __forceinline__ void load_stage64(const float* __restrict__ Ab,
                                             const float* __restrict__ Bb,
                                             uint32_t sa, uint32_t sb, int tid) {
#pragma unroll
    for (int i = 0; i < 2; i++) {
        int slot = tid + 128 * i, row = slot >> 2, cg = slot & 3;
        cp_async16(sa + (row * GP + cg * 4) * 4, Ab + row * WDIM + cg * 4);
    }
#pragma unroll
    for (int i = 0; i < 2; i++) {
        int slot = tid + 128 * i, row = slot >> 2, cg = slot & 3;
        cp_async16(sb + (row * GP + cg * 4) * 4, Bb + row * WDIM + cg * 4);
    }
}

template <int SRC>
__global__ __launch_bounds__(128) void k_gemm(const float* __restrict__ bias) {
    const float* A = (SRC == 1) ? g_H1 : g_H2;
    const float* B = (SRC == 1) ? g_W2r : g_W3r;
    __shared__ __align__(16) float As[3][64 * GP];
    __shared__ __align__(16) float Bs[3][64 * GP];

    const int tid  = threadIdx.x;
    const int warp = tid >> 5, lane = tid & 31;
    const int quad = lane >> 2, qid = lane & 3;
    const int wm = (warp >> 1) * 32, wn = (warp & 1) * 32;
    const int m0 = blockIdx.y * 64, n0 = blockIdx.x * 64;

    const float* Abase = A + m0 * WDIM;
    const float* Bbase = B + n0 * WDIM;
    const uint32_t sa0 = (uint32_t)__cvta_generic_to_shared(&As[0][0]);
    const uint32_t sb0 = (uint32_t)__cvta_generic_to_shared(&Bs[0][0]);
    const uint32_t stStride = 64 * GP * 4;

    float acc[2][4][4];
#pragma unroll
    for (int i = 0; i < 2; i++)
#pragma unroll
        for (int j = 0; j < 4; j++)
#pragma unroll
            for (int q = 0; q < 4; q++) acc[i][j][q] = 0.f;

    load_stage64(Abase, Bbase, sa0, sb0, tid);
    asm volatile("cp.async.commit_group;\n");
    load_stage64(Abase + 16, Bbase + 16, sa0 + stStride, sb0 + stStride, tid);
    asm volatile("cp.async.commit_group;\n");

    const int NT = WDIM / 16;           // 64
    int s = 0;
    for (int kt = 0; kt < NT; kt++) {
        asm volatile("cp.async.wait_group 1;\n");
        __syncthreads();
        if (kt + 2 < NT) {
            int s2 = (s + 2 >= 3) ? s - 1 : s + 2;
            load_stage64(Abase + (kt + 2) * 16, Bbase + (kt + 2) * 16,
                         sa0 + s2 * stStride, sb0 + s2 * stStride, tid);
        }
        asm volatile("cp.async.commit_group;\n");

        const float* as = &As[s][0];
        const float* bs = &Bs[s][0];
#pragma unroll
        for (int ks = 0; ks < 2; ks++) {
            int kk = ks * 8;
            uint32_t a[2][4], b[4][2];
#pragma unroll
            for (int mt = 0; mt < 2; mt++) {
                int r = wm + mt * 16 + quad;
                a[mt][0] = __float_as_uint(as[r * GP + kk + qid]);
                a[mt][1] = __float_as_uint(as[(r + 8) * GP + kk + qid]);
                a[mt][2] = __float_as_uint(as[r * GP + kk + qid + 4]);
                a[mt][3] = __float_as_uint(as[(r + 8) * GP + kk + qid + 4]);
            }
#pragma unroll
            for (int nt = 0; nt < 4; nt++) {
                int n = wn + nt * 8 + quad;
                b[nt][0] = __float_as_uint(bs[n * GP + kk + qid]);
                b[nt][1] = __float_as_uint(bs[n * GP + kk + qid + 4]);
            }
#pragma unroll
            for (int mt = 0; mt < 2; mt++)
#pragma unroll
                for (int nt = 0; nt < 4; nt++) {
                    asm volatile(
                        "mma.sync.aligned.m16n8k8.row.col.f32.tf32.tf32.f32 "
                        "{%0,%1,%2,%3}, {%4,%5,%6,%7}, {%8,%9}, {%0,%1,%2,%3};\n"
                        : "+f"(acc[mt][nt][0]), "+f"(acc[mt][nt][1]),
                          "+f"(acc[mt][nt][2]), "+f"(acc[mt][nt][3])
                        : "r"(a[mt][0]), "r"(a[mt][1]), "r"(a[mt][2]), "r"(a[mt][3]),
                          "r"(b[nt][0]), "r"(b[nt][1]));
                }
        }
        s = (s + 1 >= 3) ? 0 : s + 1;
    }

    if (SRC == 1) {
#pragma unroll
        for (int mt = 0; mt < 2; mt++) {
            int mrow = m0 + wm + mt * 16 + quad;
#pragma unroll
            for (int nt = 0; nt < 4; nt++) {
                int ncol = n0 + wn + nt * 8 + 2 * qid;
                float b0 = bias[ncol], b1 = bias[ncol + 1];
                float2 o0, o1;
                o0.x = tf32r(gelu_f(acc[mt][nt][0] + b0));
                o0.y = tf32r(gelu_f(acc[mt][nt][1] + b1));
                o1.x = tf32r(gelu_f(acc[mt][nt][2] + b0));
                o1.y = tf32r(gelu_f(acc[mt][nt][3] + b1));
                *(float2*)(g_H2 + mrow * WDIM + ncol) = o0;
                *(float2*)(g_H2 + (mrow + 8) * WDIM + ncol) = o1;
            }
        }
    } else {
        float colacc[4][2];
#pragma unroll
        for (int nt = 0; nt < 4; nt++) { colacc[nt][0] = 0.f; colacc[nt][1] = 0.f; }
#pragma unroll
        for (int nt = 0; nt < 4; nt++) {
            int ncol = n0 + wn + nt * 8 + 2 * qid;
            float b0 = bias[ncol], b1 = bias[ncol + 1];
#pragma unroll
            for (int mt = 0; mt < 2; mt++) {
                colacc[nt][0] += gelu_f(acc[mt][nt][0] + b0) + gelu_f(acc[mt][nt][2] + b0);
                colacc[nt][1] += gelu_f(acc[mt][nt][1] + b1) + gelu_f(acc[mt][nt][3] + b1);
            }
        }
#pragma unroll
        for (int nt = 0; nt < 4; nt++)
#pragma unroll
            for (int c = 0; c < 2; c++) {
                float v = colacc[nt][c];
                v += __shfl_xor_sync(0xffffffffu, v, 4);
                v += __shfl_xor_sync(0xffffffffu, v, 8);
                v += __shfl_xor_sync(0xffffffffu, v, 16);
                colacc[nt][c] = v;
            }
        if (quad == 0) {
#pragma unroll
            for (int nt = 0; nt < 4; nt++) {
                int ncol = n0 + wn + nt * 8 + 2 * qid;
                atomicAdd(&g_HSUM[ncol], colacc[nt][0]);
                atomicAdd(&g_HSUM[ncol + 1], colacc[nt][1]);
            }
        }
    }
}

// ---------------- wsum GEMV (vectorized) + scatter into 64x64 M -------------
__global__ __launch_bounds__(256) void k_wsum(const float* __restrict__ W4,
                                              const float* __restrict__ b4, float Sf) {
    int gw = (blockIdx.x * 256 + threadIdx.x) >> 5;   // 0..4095
    int lane = threadIdx.x & 31;
    const float4* wr = (const float4*)(W4 + gw * WDIM);
    const float4* hs = (const float4*)g_HSUM;
    float acc = 0.f;
#pragma unroll
    for (int it = 0; it < 8; it++) {
        float4 w = wr[lane + 32 * it];
        float4 h = hs[lane + 32 * it];
        acc += w.x * h.x + w.y * h.y + w.z * h.z + w.w * h.w;
    }
#pragma unroll
    for (int off = 16; off; off >>= 1) acc += __shfl_xor_sync(0xffffffffu, acc, off);
    if (lane == 0) {
        int c = gw >> 10, ij = gw & 1023, i = ij >> 5, j = ij & 31;
        int row = 2 * i + ((c == 1 || c == 3) ? 1 : 0);
        int col = 2 * j + ((c == 1 || c == 2) ? 1 : 0);
        g_M[row * 64 + col] = acc + Sf * b4[gw];
    }
}

// ---------------- Fourier evaluation (f32x2 packed math) --------------------
__global__ __launch_bounds__(128) void k_fourier(const float* __restrict__ r,
                                                 float* __restrict__ out, int NP) {
    __shared__ __align__(16) float sM[4096];
    for (int i = threadIdx.x; i < 4096; i += 128) sM[i] = g_M[i];
    __syncthreads();
    int n = blockIdx.x * 128 + threadIdx.x;
    if (n >= NP) return;
    float x = r[2 * n], y = r[2 * n + 1];
    const float w0 = 0.6283185307179586f;   // 2*pi/10
    float s1x, c1x, s1y, c1y;
    sincosf(w0 * x, &s1x, &c1x);
    sincosf(w0 * y, &s1y, &c1y);

    unsigned long long xd[64];
    xd[0] = pk2(c1x, c1x);
    xd[1] = pk2(s1x, s1x);
    float cc = c1x, ss = s1x;
#pragma unroll
    for (int i = 1; i < 32; i++) {
        float nc = cc * c1x - ss * s1x;
        float ns = ss * c1x + cc * s1x;
        xd[2 * i] = pk2(nc, nc);
        xd[2 * i + 1] = pk2(ns, ns);
        cc = nc; ss = ns;
    }

    uint32_t mbase = (uint32_t)__cvta_generic_to_shared(&sM[0]);
    unsigned long long acc2 = pk2(0.f, 0.f);
    float cy = c1y, sy = s1y;
#pragma unroll 1
    for (int jq = 0; jq < 16; jq++) {
        float cy2 = cy * c1y - sy * s1y;
        float sy2 = sy * c1y + cy * s1y;
        unsigned long long t01 = pk2(0.f, 0.f), t23 = pk2(0.f, 0.f);
        uint32_t addr = mbase + jq * 16;
#pragma unroll
        for (int i = 0; i < 64; i++) {
            unsigned long long m01, m23;
            asm("ld.shared.v2.b64 {%0,%1}, [%2];"
                : "=l"(m01), "=l"(m23) : "r"(addr + i * 256));
            fma2(t01, m01, xd[i]);
            fma2(t23, m23, xd[i]);
        }
        fma2(acc2, t01, pk2(cy, sy));
        fma2(acc2, t23, pk2(cy2, sy2));
        float cy3 = cy2 * c1y - sy2 * s1y;
        float sy3 = sy2 * c1y + cy2 * s1y;
        cy = cy3; sy = sy3;
    }
    float lo, hi;
    asm("mov.b64 {%0,%1}, %2;" : "=f"(lo), "=f"(hi) : "l"(acc2));
    out[n] = g_bsum + lo + hi;
}

// ---------------- launcher --------------------------------------------------
extern "C" void kernel_launch(void* const* d_in, const int* in_sizes, int n_in,
                              void* d_out, int out_size) {
    const float* sources = (const float*)d_in[0];
    const float* r       = (const float*)d_in[1];
    const float* W1      = (const float*)d_in[2];
    const float* b1      = (const float*)d_in[3];
    const float* W2      = (const float*)d_in[4];
    const float* b2      = (const float*)d_in[5];
    const float* W3      = (const float*)d_in[6];
    const float* b3      = (const float*)d_in[7];
    const float* W4      = (const float*)d_in[8];
    const float* b4      = (const float*)d_in[9];
    const float* Wb      = (const float*)d_in[10];
    const float* bb      = (const float*)d_in[11];
    float* out = (float*)d_out;

    int S  = in_sizes[0] / 4;          // 2048
    int NP = out_size;                 // 100000

    k_prep<<<12289, 256>>>(sources, W1, b1, W2, W3, Wb, bb, S);

    dim3 gg(WDIM / 64, SMAX / 64);     // (16, 32) = 512 CTAs
    k_gemm<1><<<gg, 128>>>(b2);
    k_gemm<2><<<gg, 128>>>(b3);

    k_wsum<<<512, 256>>>(W4, b4, (float)S);

    int nb = (NP + 127) / 128;
    k_fourier<<<nb, 128>>>(r, out, NP);
}

// round 10
// speedup vs baseline: 1.2855x; 1.2855x over previous
#include <cuda_runtime.h>
#include <cuda_fp16.h>
#include <math.h>
#include <stdint.h>

#define SMAX 2048
#define WDIM 1024

// ---------------- scratch (static device globals; no allocation) -------------
__device__ __half g_H1h[SMAX * WDIM];   // 4 MB
__device__ __half g_H2h[SMAX * WDIM];   // 4 MB
__device__ __half g_W2h[WDIM * WDIM];   // 2 MB (RN fp16 W2)
__device__ __half g_W3h[WDIM * WDIM];   // 2 MB (RN fp16 W3)
__device__ float g_HSUM[WDIM];
__device__ float g_M[64 * 64];
__device__ float g_bsum;

__device__ __forceinline__ float gelu_f(float x) {
    float t = tanhf(0.7978845608028654f * (x + 0.044715f * x * x * x));
    return 0.5f * x * (1.0f + t);
}

__device__ __forceinline__ void cp_async16(uint32_t dst, const void* src) {
    asm volatile("cp.async.cg.shared.global [%0], [%1], 16;\n" :: "r"(dst), "l"(src));
}

__device__ __forceinline__ unsigned long long pk2(float a, float b) {
    unsigned long long d;
    asm("mov.b64 %0, {%1, %2};" : "=l"(d) : "f"(a), "f"(b));
    return d;
}
__device__ __forceinline__ void fma2(unsigned long long& d, unsigned long long a,
                                     unsigned long long b) {
    asm("fma.rn.f32x2 %0, %1, %2, %0;" : "+l"(d) : "l"(a), "l"(b));
}

// ---------- fused prep: W2/W3 -> fp16 | layer1 -> fp16 | bsum + hsum-zero ---
__global__ void k_prep(const float* __restrict__ src, const float* __restrict__ W1,
                       const float* __restrict__ b1, const float* __restrict__ W2,
                       const float* __restrict__ W3, const float* __restrict__ Wb,
                       const float* __restrict__ bb, int S) {
    int bid = blockIdx.x;
    int tid = threadIdx.x;
    if (bid < 4096) {                       // weights: 2 x 1M elems
        int i = bid * 256 + tid;
        g_W2h[i] = __float2half_rn(W2[i]);
        g_W3h[i] = __float2half_rn(W3[i]);
    } else if (bid < 12288) {               // layer 1: 2M outputs
        int idx = (bid - 4096) * 256 + tid;
        int s = idx >> 10, o = idx & (WDIM - 1);
        float4 w  = *(const float4*)(W1 + 4 * o);
        float4 sv = *(const float4*)(src + 4 * s);
        float v = b1[o] + sv.x * w.x + sv.y * w.y + sv.z * w.z + sv.w * w.w;
        g_H1h[idx] = __float2half_rn(gelu_f(v));
    } else {                                // bias reduce + zero HSUM
        __shared__ float red[256];
        *(float4*)(g_HSUM + tid * 4) = make_float4(0.f, 0.f, 0.f, 0.f);
        float w0 = Wb[0], w1 = Wb[1], w2 = Wb[2], w3 = Wb[3];
        float acc = 0.f;
        for (int s = tid; s < S; s += 256) {
            float4 sv = *(const float4*)(src + 4 * s);
            acc += sv.x * w0 + sv.y * w1 + sv.z * w2 + sv.w * w3;
        }
        red[tid] = acc;
        __syncthreads();
        for (int off = 128; off > 0; off >>= 1) {
            if (tid < off) red[tid] += red[tid + off];
            __syncthreads();
        }
        if (tid == 0) g_bsum = red[0] + (float)S * bb[0];
    }
}

// ---------------- fp16 tensor-core GEMM: C = gelu(A @ B^T + bias) -----------
// CTA tile 128x64 (round-4 winning schedule), 128 threads = 4 warps (2x2),
// warp tile 64x32. 3-stage cp.async, BK=16 -> ONE m16n8k16 k-step per tile.
// fp16 has the same 10-bit mantissa as tf32 -> identical rounding error,
// but 2x MAC/instr on the legacy mma path. fp32 accumulate.
// SRC==1: A=g_H1h, B=g_W2h -> store fp16(gelu) to g_H2h.
// SRC==2: A=g_H2h, B=g_W3h -> fused column-sum of gelu into g_HSUM.
#define HP 24   // smem pitch in halves (48 B): conflict-free for frag pattern

__device__ __forceinline__ void load_stage(const __half* __restrict__ Ab,
                                           const __half* __restrict__ Bb,
                                           uint32_t sa, uint32_t sb, int tid) {
#pragma unroll
    for (int i = 0; i < 2; i++) {           // A: 128 rows x 32 B = 256 chunks
        int slot = tid + 128 * i, row = slot >> 1, h = slot & 1;
        cp_async16(sa + row * 48 + h * 16, Ab + row * WDIM + h * 8);
    }
    {                                       // B: 64 rows x 32 B = 128 chunks
        int row = tid >> 1, h = tid & 1;
        cp_async16(sb + row * 48 + h * 16, Bb + row * WDIM + h * 8);
    }
}

template <int SRC>
__global__ __launch_bounds__(128) void k_gemm(const float* __restrict__ bias) {
    const __half* A = (SRC == 1) ? g_H1h : g_H2h;
    const __half* B = (SRC == 1) ? g_W2h : g_W3h;
    __shared__ __align__(16) __half As[3][128 * HP];
    __shared__ __align__(16) __half Bs[3][64 * HP];

    const int tid  = threadIdx.x;
    const int warp = tid >> 5, lane = tid & 31;
    const int quad = lane >> 2, qid = lane & 3;
    const int wm = (warp >> 1) * 64, wn = (warp & 1) * 32;
    const int m0 = blockIdx.y * 128, n0 = blockIdx.x * 64;

    const __half* Abase = A + m0 * WDIM;
    const __half* Bbase = B + n0 * WDIM;
    const uint32_t sa0 = (uint32_t)__cvta_generic_to_shared(&As[0][0]);
    const uint32_t sb0 = (uint32_t)__cvta_generic_to_shared(&Bs[0][0]);
    const uint32_t saStride = 128 * 48, sbStride = 64 * 48;

    float acc[4][4][4];
#pragma unroll
    for (int i = 0; i < 4; i++)
#pragma unroll
        for (int j = 0; j < 4; j++)
#pragma unroll
            for (int q = 0; q < 4; q++) acc[i][j][q] = 0.f;

    load_stage(Abase, Bbase, sa0, sb0, tid);
    asm volatile("cp.async.commit_group;\n");
    load_stage(Abase + 16, Bbase + 16, sa0 + saStride, sb0 + sbStride, tid);
    asm volatile("cp.async.commit_group;\n");

    const int NT = WDIM / 16;           // 64
    int s = 0;
    for (int kt = 0; kt < NT; kt++) {
        asm volatile("cp.async.wait_group 1;\n");
        __syncthreads();
        if (kt + 2 < NT) {
            int s2 = (s + 2 >= 3) ? s - 1 : s + 2;
            load_stage(Abase + (kt + 2) * 16, Bbase + (kt + 2) * 16,
                       sa0 + s2 * saStride, sb0 + s2 * sbStride, tid);
        }
        asm volatile("cp.async.commit_group;\n");

        const __half* as = &As[s][0];
        const __half* bs = &Bs[s][0];
        uint32_t a[4][4], b[4][2];
#pragma unroll
        for (int mt = 0; mt < 4; mt++) {
            int r = wm + mt * 16 + quad;
            a[mt][0] = *(const uint32_t*)&as[r * HP + 2 * qid];
            a[mt][1] = *(const uint32_t*)&as[(r + 8) * HP + 2 * qid];
            a[mt][2] = *(const uint32_t*)&as[r * HP + 2 * qid + 8];
            a[mt][3] = *(const uint32_t*)&as[(r + 8) * HP + 2 * qid + 8];
        }
#pragma unroll
        for (int nt = 0; nt < 4; nt++) {
            int n = wn + nt * 8 + quad;
            b[nt][0] = *(const uint32_t*)&bs[n * HP + 2 * qid];
            b[nt][1] = *(const uint32_t*)&bs[n * HP + 2 * qid + 8];
        }
#pragma unroll
        for (int mt = 0; mt < 4; mt++)
#pragma unroll
            for (int nt = 0; nt < 4; nt++) {
                asm volatile(
                    "mma.sync.aligned.m16n8k16.row.col.f32.f16.f16.f32 "
                    "{%0,%1,%2,%3}, {%4,%5,%6,%7}, {%8,%9}, {%0,%1,%2,%3};\n"
                    : "+f"(acc[mt][nt][0]), "+f"(acc[mt][nt][1]),
                      "+f"(acc[mt][nt][2]), "+f"(acc[mt][nt][3])
                    : "r"(a[mt][0]), "r"(a[mt][1]), "r"(a[mt][2]), "r"(a[mt][3]),
                      "r"(b[nt][0]), "r"(b[nt][1]));
            }
        s = (s + 1 >= 3) ? 0 : s + 1;
    }

    if (SRC == 1) {
#pragma unroll
        for (int mt = 0; mt < 4; mt++) {
            int mrow = m0 + wm + mt * 16 + quad;
#pragma unroll
            for (int nt = 0; nt < 4; nt++) {
                int ncol = n0 + wn + nt * 8 + 2 * qid;
                float b0 = bias[ncol], b1 = bias[ncol + 1];
                *(half2*)(g_H2h + mrow * WDIM + ncol) =
                    __floats2half2_rn(gelu_f(acc[mt][nt][0] + b0),
                                      gelu_f(acc[mt][nt][1] + b1));
                *(half2*)(g_H2h + (mrow + 8) * WDIM + ncol) =
                    __floats2half2_rn(gelu_f(acc[mt][nt][2] + b0),
                                      gelu_f(acc[mt][nt][3] + b1));
            }
        }
    } else {
        float colacc[4][2];
#pragma unroll
        for (int nt = 0; nt < 4; nt++) { colacc[nt][0] = 0.f; colacc[nt][1] = 0.f; }
#pragma unroll
        for (int nt = 0; nt < 4; nt++) {
            int ncol = n0 + wn + nt * 8 + 2 * qid;
            float b0 = bias[ncol], b1 = bias[ncol + 1];
#pragma unroll
            for (int mt = 0; mt < 4; mt++) {
                colacc[nt][0] += gelu_f(acc[mt][nt][0] + b0) + gelu_f(acc[mt][nt][2] + b0);
                colacc[nt][1] += gelu_f(acc[mt][nt][1] + b1) + gelu_f(acc[mt][nt][3] + b1);
            }
        }
#pragma unroll
        for (int nt = 0; nt < 4; nt++)
#pragma unroll
            for (int c = 0; c < 2; c++) {
                float v = colacc[nt][c];
                v += __shfl_xor_sync(0xffffffffu, v, 4);
                v += __shfl_xor_sync(0xffffffffu, v, 8);
                v += __shfl_xor_sync(0xffffffffu, v, 16);
                colacc[nt][c] = v;
            }
        if (quad == 0) {
#pragma unroll
            for (int nt = 0; nt < 4; nt++) {
                int ncol = n0 + wn + nt * 8 + 2 * qid;
                atomicAdd(&g_HSUM[ncol], colacc[nt][0]);
                atomicAdd(&g_HSUM[ncol + 1], colacc[nt][1]);
            }
        }
    }
}

// ---------------- wsum GEMV (vectorized) + scatter into 64x64 M -------------
__global__ __launch_bounds__(256) void k_wsum(const float* __restrict__ W4,
                                              const float* __restrict__ b4, float Sf) {
    int gw = (blockIdx.x * 256 + threadIdx.x) >> 5;   // 0..4095
    int lane = threadIdx.x & 31;
    const float4* wr = (const float4*)(W4 + gw * WDIM);
    const float4* hs = (const float4*)g_HSUM;
    float acc = 0.f;
#pragma unroll
    for (int it = 0; it < 8; it++) {
        float4 w = wr[lane + 32 * it];
        float4 h = hs[lane + 32 * it];
        acc += w.x * h.x + w.y * h.y + w.z * h.z + w.w * h.w;
    }
#pragma unroll
    for (int off = 16; off; off >>= 1) acc += __shfl_xor_sync(0xffffffffu, acc, off);
    if (lane == 0) {
        int c = gw >> 10, ij = gw & 1023, i = ij >> 5, j = ij & 31;
        int row = 2 * i + ((c == 1 || c == 3) ? 1 : 0);
        int col = 2 * j + ((c == 1 || c == 2) ? 1 : 0);
        g_M[row * 64 + col] = acc + Sf * b4[gw];
    }
}

// ---------------- Fourier evaluation (f32x2 packed math) --------------------
__global__ __launch_bounds__(128) void k_fourier(const float* __restrict__ r,
                                                 float* __restrict__ out, int NP) {
    __shared__ __align__(16) float sM[4096];
    for (int i = threadIdx.x; i < 4096; i += 128) sM[i] = g_M[i];
    __syncthreads();
    int n = blockIdx.x * 128 + threadIdx.x;
    if (n >= NP) return;
    float x = r[2 * n], y = r[2 * n + 1];
    const float w0 = 0.6283185307179586f;   // 2*pi/10
    float s1x, c1x, s1y, c1y;
    sincosf(w0 * x, &s1x, &c1x);
    sincosf(w0 * y, &s1y, &c1y);

    unsigned long long xd[64];
    xd[0] = pk2(c1x, c1x);
    xd[1] = pk2(s1x, s1x);
    float cc = c1x, ss = s1x;
#pragma unroll
    for (int i = 1; i < 32; i++) {
        float nc = cc * c1x - ss * s1x;
        float ns = ss * c1x + cc * s1x;
        xd[2 * i] = pk2(nc, nc);
        xd[2 * i + 1] = pk2(ns, ns);
        cc = nc; ss = ns;
    }

    uint32_t mbase = (uint32_t)__cvta_generic_to_shared(&sM[0]);
    unsigned long long acc2 = pk2(0.f, 0.f);
    float cy = c1y, sy = s1y;
#pragma unroll 1
    for (int jq = 0; jq < 16; jq++) {
        float cy2 = cy * c1y - sy * s1y;
        float sy2 = sy * c1y + cy * s1y;
        unsigned long long t01 = pk2(0.f, 0.f), t23 = pk2(0.f, 0.f);
        uint32_t addr = mbase + jq * 16;
#pragma unroll
        for (int i = 0; i < 64; i++) {
            unsigned long long m01, m23;
            asm("ld.shared.v2.b64 {%0,%1}, [%2];"
                : "=l"(m01), "=l"(m23) : "r"(addr + i * 256));
            fma2(t01, m01, xd[i]);
            fma2(t23, m23, xd[i]);
        }
        fma2(acc2, t01, pk2(cy, sy));
        fma2(acc2, t23, pk2(cy2, sy2));
        float cy3 = cy2 * c1y - sy2 * s1y;
        float sy3 = sy2 * c1y + cy2 * s1y;
        cy = cy3; sy = sy3;
    }
    float lo, hi;
    asm("mov.b64 {%0,%1}, %2;" : "=f"(lo), "=f"(hi) : "l"(acc2));
    out[n] = g_bsum + lo + hi;
}

// ---------------- launcher --------------------------------------------------
extern "C" void kernel_launch(void* const* d_in, const int* in_sizes, int n_in,
                              void* d_out, int out_size) {
    const float* sources = (const float*)d_in[0];
    const float* r       = (const float*)d_in[1];
    const float* W1      = (const float*)d_in[2];
    const float* b1      = (const float*)d_in[3];
    const float* W2      = (const float*)d_in[4];
    const float* b2      = (const float*)d_in[5];
    const float* W3      = (const float*)d_in[6];
    const float* b3      = (const float*)d_in[7];
    const float* W4      = (const float*)d_in[8];
    const float* b4      = (const float*)d_in[9];
    const float* Wb      = (const float*)d_in[10];
    const float* bb      = (const float*)d_in[11];
    float* out = (float*)d_out;

    int S  = in_sizes[0] / 4;          // 2048
    int NP = out_size;                 // 100000

    k_prep<<<12289, 256>>>(sources, W1, b1, W2, W3, Wb, bb, S);

    dim3 gg(WDIM / 64, SMAX / 128);    // (16, 16) = 256 CTAs
    k_gemm<1><<<gg, 128>>>(b2);
    k_gemm<2><<<gg, 128>>>(b3);

    k_wsum<<<512, 256>>>(W4, b4, (float)S);

    int nb = (NP + 127) / 128;
    k_fourier<<<nb, 128>>>(r, out, NP);
}

// round 13
// speedup vs baseline: 1.5422x; 1.1997x over previous
#include <cuda_runtime.h>
#include <cuda_fp16.h>
#include <math.h>
#include <stdint.h>

#define SMAX 2048
#define WDIM 1024

// ---------------- scratch (static device globals; no allocation) -------------
__device__ __half g_H1h[SMAX * WDIM];   // 4 MB
__device__ __half g_H2h[SMAX * WDIM];   // 4 MB
__device__ __half g_W2h[WDIM * WDIM];   // 2 MB
__device__ __half g_W3h[WDIM * WDIM];   // 2 MB
__device__ float g_HSUM[WDIM];
__device__ float g_M[64 * 64];
__device__ float g_bsum;

__device__ __forceinline__ float gelu_f(float x) {
    float t = tanhf(0.7978845608028654f * (x + 0.044715f * x * x * x));
    return 0.5f * x * (1.0f + t);
}

__device__ __forceinline__ void cp_async16(uint32_t dst, const void* src) {
    asm volatile("cp.async.cg.shared.global [%0], [%1], 16;\n" :: "r"(dst), "l"(src));
}

__device__ __forceinline__ unsigned long long pk2(float a, float b) {
    unsigned long long d;
    asm("mov.b64 %0, {%1, %2};" : "=l"(d) : "f"(a), "f"(b));
    return d;
}
__device__ __forceinline__ void fma2(unsigned long long& d, unsigned long long a,
                                     unsigned long long b) {
    asm("fma.rn.f32x2 %0, %1, %2, %0;" : "+l"(d) : "l"(a), "l"(b));
}

// ---------- fused prep: W2/W3 -> fp16 (vec) | layer1 -> fp16 | bsum ---------
__global__ void k_prep(const float* __restrict__ src, const float* __restrict__ W1,
                       const float* __restrict__ b1, const float* __restrict__ W2,
                       const float* __restrict__ W3, const float* __restrict__ Wb,
                       const float* __restrict__ bb, int S) {
    int bid = blockIdx.x;
    int tid = threadIdx.x;
    if (bid < 1024) {                       // weights: 1M elems x2, 4 per thread
        int i4 = (bid * 256 + tid) * 4;
        float4 w2 = *(const float4*)(W2 + i4);
        float4 w3 = *(const float4*)(W3 + i4);
        __half2 a0 = __floats2half2_rn(w2.x, w2.y);
        __half2 a1 = __floats2half2_rn(w2.z, w2.w);
        __half2 b0 = __floats2half2_rn(w3.x, w3.y);
        __half2 b1h = __floats2half2_rn(w3.z, w3.w);
        *(uint2*)(g_W2h + i4) = make_uint2(*(uint32_t*)&a0, *(uint32_t*)&a1);
        *(uint2*)(g_W3h + i4) = make_uint2(*(uint32_t*)&b0, *(uint32_t*)&b1h);
    } else if (bid < 9216) {                // layer 1: 2M outputs
        int idx = (bid - 1024) * 256 + tid;
        int s = idx >> 10, o = idx & (WDIM - 1);
        float4 w  = *(const float4*)(W1 + 4 * o);
        float4 sv = *(const float4*)(src + 4 * s);
        float v = b1[o] + sv.x * w.x + sv.y * w.y + sv.z * w.z + sv.w * w.w;
        g_H1h[idx] = __float2half_rn(gelu_f(v));
    } else {                                // bias reduce + zero HSUM
        __shared__ float red[256];
        *(float4*)(g_HSUM + tid * 4) = make_float4(0.f, 0.f, 0.f, 0.f);
        float w0 = Wb[0], w1 = Wb[1], w2 = Wb[2], w3 = Wb[3];
        float acc = 0.f;
        for (int s = tid; s < S; s += 256) {
            float4 sv = *(const float4*)(src + 4 * s);
            acc += sv.x * w0 + sv.y * w1 + sv.z * w2 + sv.w * w3;
        }
        red[tid] = acc;
        __syncthreads();
        for (int off = 128; off > 0; off >>= 1) {
            if (tid < off) red[tid] += red[tid + off];
            __syncthreads();
        }
        if (tid == 0) g_bsum = red[0] + (float)S * bb[0];
    }
}

// ---------------- fp16 tensor-core GEMM: C = gelu(A @ B^T + bias) -----------
// CTA tile 128x64, 128 threads = 4 warps (2x2), warp tile 64x32.
// BK=32 (two m16n8k16 k-steps per stage -> 32 iters, half the barriers),
// 3-stage cp.async. fp32 accumulate. grid (16,16) = 256 CTAs.
// SRC==1: A=g_H1h, B=g_W2h -> store fp16(gelu) to g_H2h.
// SRC==2: A=g_H2h, B=g_W3h -> fused column-sum of gelu into g_HSUM.
#define HP2 40   // smem pitch in halves (80 B): conflict-free for 32b frag loads

__device__ __forceinline__ void load_stage(const __half* __restrict__ Ab,
                                           const __half* __restrict__ Bb,
                                           uint32_t sa, uint32_t sb, int tid) {
#pragma unroll
    for (int i = 0; i < 4; i++) {           // A: 128 rows x 64 B = 512 chunks
        int slot = tid + 128 * i, row = slot >> 2, h = slot & 3;
        cp_async16(sa + (row * HP2 + h * 8) * 2, Ab + row * WDIM + h * 8);
    }
#pragma unroll
    for (int i = 0; i < 2; i++) {           // B: 64 rows x 64 B = 256 chunks
        int slot = tid + 128 * i, row = slot >> 2, h = slot & 3;
        cp_async16(sb + (row * HP2 + h * 8) * 2, Bb + row * WDIM + h * 8);
    }
}

template <int SRC>
__global__ __launch_bounds__(128) void k_gemm(const float* __restrict__ bias) {
    const __half* A = (SRC == 1) ? g_H1h : g_H2h;
    const __half* B = (SRC == 1) ? g_W2h : g_W3h;
    __shared__ __align__(16) __half As[3][128 * HP2];   // 30.0 KB
    __shared__ __align__(16) __half Bs[3][64 * HP2];    // 15.0 KB

    const int tid  = threadIdx.x;
    const int warp = tid >> 5, lane = tid & 31;
    const int quad = lane >> 2, qid = lane & 3;
    const int wm = (warp >> 1) * 64, wn = (warp & 1) * 32;
    const int m0 = blockIdx.y * 128, n0 = blockIdx.x * 64;

    const __half* Abase = A + m0 * WDIM;
    const __half* Bbase = B + n0 * WDIM;
    const uint32_t sa0 = (uint32_t)__cvta_generic_to_shared(&As[0][0]);
    const uint32_t sb0 = (uint32_t)__cvta_generic_to_shared(&Bs[0][0]);
    const uint32_t saStride = 128 * HP2 * 2, sbStride = 64 * HP2 * 2;

    float acc[4][4][4];
#pragma unroll
    for (int i = 0; i < 4; i++)
#pragma unroll
        for (int j = 0; j < 4; j++)
#pragma unroll
            for (int q = 0; q < 4; q++) acc[i][j][q] = 0.f;

    load_stage(Abase, Bbase, sa0, sb0, tid);
    asm volatile("cp.async.commit_group;\n");
    load_stage(Abase + 32, Bbase + 32, sa0 + saStride, sb0 + sbStride, tid);
    asm volatile("cp.async.commit_group;\n");

    const int NT = WDIM / 32;           // 32 iterations
    int s = 0;
    for (int kt = 0; kt < NT; kt++) {
        asm volatile("cp.async.wait_group 1;\n");
        __syncthreads();
        if (kt + 2 < NT) {
            int s2 = (s + 2 >= 3) ? s - 1 : s + 2;
            load_stage(Abase + (kt + 2) * 32, Bbase + (kt + 2) * 32,
                       sa0 + s2 * saStride, sb0 + s2 * sbStride, tid);
        }
        asm volatile("cp.async.commit_group;\n");

        const __half* as = &As[s][0];
        const __half* bs = &Bs[s][0];
#pragma unroll
        for (int ks = 0; ks < 2; ks++) {
            const int kk = ks * 16;
            uint32_t a[4][4], b[4][2];
#pragma unroll
            for (int mt = 0; mt < 4; mt++) {
                int r = wm + mt * 16 + quad;
                a[mt][0] = *(const uint32_t*)&as[r * HP2 + kk + 2 * qid];
                a[mt][1] = *(const uint32_t*)&as[(r + 8) * HP2 + kk + 2 * qid];
                a[mt][2] = *(const uint32_t*)&as[r * HP2 + kk + 2 * qid + 8];
                a[mt][3] = *(const uint32_t*)&as[(r + 8) * HP2 + kk + 2 * qid + 8];
            }
#pragma unroll
            for (int nt = 0; nt < 4; nt++) {
                int n = wn + nt * 8 + quad;
                b[nt][0] = *(const uint32_t*)&bs[n * HP2 + kk + 2 * qid];
                b[nt][1] = *(const uint32_t*)&bs[n * HP2 + kk + 2 * qid + 8];
            }
#pragma unroll
            for (int mt = 0; mt < 4; mt++)
#pragma unroll
                for (int nt = 0; nt < 4; nt++) {
                    asm volatile(
                        "mma.sync.aligned.m16n8k16.row.col.f32.f16.f16.f32 "
                        "{%0,%1,%2,%3}, {%4,%5,%6,%7}, {%8,%9}, {%0,%1,%2,%3};\n"
                        : "+f"(acc[mt][nt][0]), "+f"(acc[mt][nt][1]),
                          "+f"(acc[mt][nt][2]), "+f"(acc[mt][nt][3])
                        : "r"(a[mt][0]), "r"(a[mt][1]), "r"(a[mt][2]), "r"(a[mt][3]),
                          "r"(b[nt][0]), "r"(b[nt][1]));
                }
        }
        s = (s + 1 >= 3) ? 0 : s + 1;
    }

    if (SRC == 1) {
#pragma unroll
        for (int mt = 0; mt < 4; mt++) {
            int mrow = m0 + wm + mt * 16 + quad;
#pragma unroll
            for (int nt = 0; nt < 4; nt++) {
                int ncol = n0 + wn + nt * 8 + 2 * qid;
                float b0 = bias[ncol], b1 = bias[ncol + 1];
                *(half2*)(g_H2h + mrow * WDIM + ncol) =
                    __floats2half2_rn(gelu_f(acc[mt][nt][0] + b0),
                                      gelu_f(acc[mt][nt][1] + b1));
                *(half2*)(g_H2h + (mrow + 8) * WDIM + ncol) =
                    __floats2half2_rn(gelu_f(acc[mt][nt][2] + b0),
                                      gelu_f(acc[mt][nt][3] + b1));
            }
        }
    } else {
        float colacc[4][2];
#pragma unroll
        for (int nt = 0; nt < 4; nt++) { colacc[nt][0] = 0.f; colacc[nt][1] = 0.f; }
#pragma unroll
        for (int nt = 0; nt < 4; nt++) {
            int ncol = n0 + wn + nt * 8 + 2 * qid;
            float b0 = bias[ncol], b1 = bias[ncol + 1];
#pragma unroll
            for (int mt = 0; mt < 4; mt++) {
                colacc[nt][0] += gelu_f(acc[mt][nt][0] + b0) + gelu_f(acc[mt][nt][2] + b0);
                colacc[nt][1] += gelu_f(acc[mt][nt][1] + b1) + gelu_f(acc[mt][nt][3] + b1);
            }
        }
#pragma unroll
        for (int nt = 0; nt < 4; nt++)
#pragma unroll
            for (int c = 0; c < 2; c++) {
                float v = colacc[nt][c];
                v += __shfl_xor_sync(0xffffffffu, v, 4);
                v += __shfl_xor_sync(0xffffffffu, v, 8);
                v += __shfl_xor_sync(0xffffffffu, v, 16);
                colacc[nt][c] = v;
            }
        if (quad == 0) {
#pragma unroll
            for (int nt = 0; nt < 4; nt++) {
                int ncol = n0 + wn + nt * 8 + 2 * qid;
                atomicAdd(&g_HSUM[ncol], colacc[nt][0]);
                atomicAdd(&g_HSUM[ncol + 1], colacc[nt][1]);
            }
        }
    }
}

// ------ wsum GEMV: HSUM in smem, all 8 W4 LDG.128 batched (full MLP) --------
__global__ __launch_bounds__(256) void k_wsum(const float* __restrict__ W4,
                                              const float* __restrict__ b4, float Sf) {
    __shared__ float sh[WDIM];
    for (int i = threadIdx.x; i < WDIM; i += 256) sh[i] = g_HSUM[i];
    __syncthreads();
    int gw = (blockIdx.x * 256 + threadIdx.x) >> 5;   // 0..4095
    int lane = threadIdx.x & 31;
    const float4* wr = (const float4*)(W4 + gw * WDIM);
    float4 w[8];
#pragma unroll
    for (int it = 0; it < 8; it++) w[it] = wr[lane + 32 * it];   // batched LDGs
    float acc = 0.f;
#pragma unroll
    for (int it = 0; it < 8; it++) {
        const float* hp = sh + (lane + 32 * it) * 4;
        acc += w[it].x * hp[0] + w[it].y * hp[1] + w[it].z * hp[2] + w[it].w * hp[3];
    }
#pragma unroll
    for (int off = 16; off; off >>= 1) acc += __shfl_xor_sync(0xffffffffu, acc, off);
    if (lane == 0) {
        int c = gw >> 10, ij = gw & 1023, i = ij >> 5, j = ij & 31;
        int row = 2 * i + ((c == 1 || c == 3) ? 1 : 0);
        int col = 2 * j + ((c == 1 || c == 2) ? 1 : 0);
        g_M[row * 64 + col] = acc + Sf * b4[gw];
    }
}

// ---------------- Fourier evaluation (f32x2 packed math) --------------------
__global__ __launch_bounds__(128) void k_fourier(const float* __restrict__ r,
                                                 float* __restrict__ out, int NP) {
    __shared__ __align__(16) float sM[4096];
    for (int i = threadIdx.x; i < 4096; i += 128) sM[i] = g_M[i];
    __syncthreads();
    int n = blockIdx.x * 128 + threadIdx.x;
    if (n >= NP) return;
    float x = r[2 * n], y = r[2 * n + 1];
    const float w0 = 0.6283185307179586f;   // 2*pi/10
    float s1x, c1x, s1y, c1y;
    sincosf(w0 * x, &s1x, &c1x);
    sincosf(w0 * y, &s1y, &c1y);

    unsigned long long xd[64];
    xd[0] = pk2(c1x, c1x);
    xd[1] = pk2(s1x, s1x);
    float cc = c1x, ss = s1x;
#pragma unroll
    for (int i = 1; i < 32; i++) {
        float nc = cc * c1x - ss * s1x;
        float ns = ss * c1x + cc * s1x;
        xd[2 * i] = pk2(nc, nc);
        xd[2 * i + 1] = pk2(ns, ns);
        cc = nc; ss = ns;
    }

    uint32_t mbase = (uint32_t)__cvta_generic_to_shared(&sM[0]);
    unsigned long long acc2 = pk2(0.f, 0.f);
    float cy = c1y, sy = s1y;
#pragma unroll 1
    for (int jq = 0; jq < 16; jq++) {
        float cy2 = cy * c1y - sy * s1y;
        float sy2 = sy * c1y + cy * s1y;
        unsigned long long t01 = pk2(0.f, 0.f), t23 = pk2(0.f, 0.f);
        uint32_t addr = mbase + jq * 16;
#pragma unroll
        for (int i = 0; i < 64; i++) {
            unsigned long long m01, m23;
            asm("ld.shared.v2.b64 {%0,%1}, [%2];"
                : "=l"(m01), "=l"(m23) : "r"(addr + i * 256));
            fma2(t01, m01, xd[i]);
            fma2(t23, m23, xd[i]);
        }
        fma2(acc2, t01, pk2(cy, sy));
        fma2(acc2, t23, pk2(cy2, sy2));
        float cy3 = cy2 * c1y - sy2 * s1y;
        float sy3 = sy2 * c1y + cy2 * s1y;
        cy = cy3; sy = sy3;
    }
    float lo, hi;
    asm("mov.b64 {%0,%1}, %2;" : "=f"(lo), "=f"(hi) : "l"(acc2));
    out[n] = g_bsum + lo + hi;
}

// ---------------- launcher --------------------------------------------------
extern "C" void kernel_launch(void* const* d_in, const int* in_sizes, int n_in,
                              void* d_out, int out_size) {
    const float* sources = (const float*)d_in[0];
    const float* r       = (const float*)d_in[1];
    const float* W1      = (const float*)d_in[2];
    const float* b1      = (const float*)d_in[3];
    const float* W2      = (const float*)d_in[4];
    const float* b2      = (const float*)d_in[5];
    const float* W3      = (const float*)d_in[6];
    const float* b3      = (const float*)d_in[7];
    const float* W4      = (const float*)d_in[8];
    const float* b4      = (const float*)d_in[9];
    const float* Wb      = (const float*)d_in[10];
    const float* bb      = (const float*)d_in[11];
    float* out = (float*)d_out;

    int S  = in_sizes[0] / 4;          // 2048
    int NP = out_size;                 // 100000

    k_prep<<<9217, 256>>>(sources, W1, b1, W2, W3, Wb, bb, S);

    dim3 gg(WDIM / 64, SMAX / 128);    // (16, 16) = 256 CTAs
    k_gemm<1><<<gg, 128>>>(b2);
    k_gemm<2><<<gg, 128>>>(b3);

    k_wsum<<<512, 256>>>(W4, b4, (float)S);

    int nb = (NP + 127) / 128;
    k_fourier<<<nb, 128>>>(r, out, NP);
}

// round 14
// speedup vs baseline: 1.6065x; 1.0417x over previous
#include <cuda_runtime.h>
#include <cuda_fp16.h>
#include <math.h>
#include <stdint.h>

#define SMAX 2048
#define WDIM 1024

// ---------------- scratch (static device globals; no allocation) -------------
__device__ __half g_H1h[SMAX * WDIM];   // 4 MB
__device__ __half g_H2h[SMAX * WDIM];   // 4 MB
__device__ __half g_W2h[WDIM * WDIM];   // 2 MB
__device__ __half g_W3h[WDIM * WDIM];   // 2 MB
__device__ float g_HSUM[WDIM];
__device__ float g_M[64 * 64];
__device__ float g_bsum;

__device__ __forceinline__ float gelu_f(float x) {
    float t = tanhf(0.7978845608028654f * (x + 0.044715f * x * x * x));
    return 0.5f * x * (1.0f + t);
}

__device__ __forceinline__ void cp_async16(uint32_t dst, const void* src) {
    asm volatile("cp.async.cg.shared.global [%0], [%1], 16;\n" :: "r"(dst), "l"(src));
}

__device__ __forceinline__ unsigned long long pk2(float a, float b) {
    unsigned long long d;
    asm("mov.b64 %0, {%1, %2};" : "=l"(d) : "f"(a), "f"(b));
    return d;
}
__device__ __forceinline__ void fma2(unsigned long long& d, unsigned long long a,
                                     unsigned long long b) {
    asm("fma.rn.f32x2 %0, %1, %2, %0;" : "+l"(d) : "l"(a), "l"(b));
}

#define LDSM4(r0, r1, r2, r3, addr) \
    asm volatile("ldmatrix.sync.aligned.m8n8.x4.shared.b16 {%0,%1,%2,%3}, [%4];" \
                 : "=r"(r0), "=r"(r1), "=r"(r2), "=r"(r3) : "r"(addr))

// ---------- fused prep: W2/W3 -> fp16 (vec) | layer1 -> fp16 | bsum ---------
__global__ void k_prep(const float* __restrict__ src, const float* __restrict__ W1,
                       const float* __restrict__ b1, const float* __restrict__ W2,
                       const float* __restrict__ W3, const float* __restrict__ Wb,
                       const float* __restrict__ bb, int S) {
    int bid = blockIdx.x;
    int tid = threadIdx.x;
    if (bid < 1024) {                       // weights: 1M elems x2, 4 per thread
        int i4 = (bid * 256 + tid) * 4;
        float4 w2 = *(const float4*)(W2 + i4);
        float4 w3 = *(const float4*)(W3 + i4);
        __half2 a0 = __floats2half2_rn(w2.x, w2.y);
        __half2 a1 = __floats2half2_rn(w2.z, w2.w);
        __half2 b0 = __floats2half2_rn(w3.x, w3.y);
        __half2 b1h = __floats2half2_rn(w3.z, w3.w);
        *(uint2*)(g_W2h + i4) = make_uint2(*(uint32_t*)&a0, *(uint32_t*)&a1);
        *(uint2*)(g_W3h + i4) = make_uint2(*(uint32_t*)&b0, *(uint32_t*)&b1h);
    } else if (bid < 9216) {                // layer 1: 2M outputs
        int idx = (bid - 1024) * 256 + tid;
        int s = idx >> 10, o = idx & (WDIM - 1);
        float4 w  = *(const float4*)(W1 + 4 * o);
        float4 sv = *(const float4*)(src + 4 * s);
        float v = b1[o] + sv.x * w.x + sv.y * w.y + sv.z * w.z + sv.w * w.w;
        g_H1h[idx] = __float2half_rn(gelu_f(v));
    } else {                                // bias reduce + zero HSUM
        __shared__ float red[256];
        *(float4*)(g_HSUM + tid * 4) = make_float4(0.f, 0.f, 0.f, 0.f);
        float w0 = Wb[0], w1 = Wb[1], w2 = Wb[2], w3 = Wb[3];
        float acc = 0.f;
        for (int s = tid; s < S; s += 256) {
            float4 sv = *(const float4*)(src + 4 * s);
            acc += sv.x * w0 + sv.y * w1 + sv.z * w2 + sv.w * w3;
        }
        red[tid] = acc;
        __syncthreads();
        for (int off = 128; off > 0; off >>= 1) {
            if (tid < off) red[tid] += red[tid + off];
            __syncthreads();
        }
        if (tid == 0) g_bsum = red[0] + (float)S * bb[0];
    }
}

// ---------------- fp16 tensor-core GEMM: C = gelu(A @ B^T + bias) -----------
// CTA tile 128x64, 128 threads = 4 warps (2x2), warp tile 64x32, BK=32,
// 3-stage cp.async. Fragment loads via ldmatrix.x4: 12 LDSM vs 48 LDS32
// per k-iteration (issue-slot bound -> 4x cut in front-end traffic).
// SRC==1: A=g_H1h, B=g_W2h -> store fp16(gelu) to g_H2h.
// SRC==2: A=g_H2h, B=g_W3h -> fused column-sum of gelu into g_HSUM.
#define HP2 40   // smem pitch in halves (80 B): 8 rows @ 80B cover all 32 banks

__device__ __forceinline__ void load_stage(const __half* __restrict__ Ab,
                                           const __half* __restrict__ Bb,
                                           uint32_t sa, uint32_t sb, int tid) {
#pragma unroll
    for (int i = 0; i < 4; i++) {           // A: 128 rows x 64 B = 512 chunks
        int slot = tid + 128 * i, row = slot >> 2, h = slot & 3;
        cp_async16(sa + (row * HP2 + h * 8) * 2, Ab + row * WDIM + h * 8);
    }
#pragma unroll
    for (int i = 0; i < 2; i++) {           // B: 64 rows x 64 B = 256 chunks
        int slot = tid + 128 * i, row = slot >> 2, h = slot & 3;
        cp_async16(sb + (row * HP2 + h * 8) * 2, Bb + row * WDIM + h * 8);
    }
}

template <int SRC>
__global__ __launch_bounds__(128) void k_gemm(const float* __restrict__ bias) {
    const __half* A = (SRC == 1) ? g_H1h : g_H2h;
    const __half* B = (SRC == 1) ? g_W2h : g_W3h;
    __shared__ __align__(16) __half As[3][128 * HP2];   // 30.0 KB
    __shared__ __align__(16) __half Bs[3][64 * HP2];    // 15.0 KB

    const int tid  = threadIdx.x;
    const int warp = tid >> 5, lane = tid & 31;
    const int quad = lane >> 2, qid = lane & 3;
    const int wm = (warp >> 1) * 64, wn = (warp & 1) * 32;
    const int m0 = blockIdx.y * 128, n0 = blockIdx.x * 64;

    const __half* Abase = A + m0 * WDIM;
    const __half* Bbase = B + n0 * WDIM;
    const uint32_t sa0 = (uint32_t)__cvta_generic_to_shared(&As[0][0]);
    const uint32_t sb0 = (uint32_t)__cvta_generic_to_shared(&Bs[0][0]);
    const uint32_t saStride = 128 * HP2 * 2, sbStride = 64 * HP2 * 2;

    // ldmatrix per-lane source offsets (bytes). matrix m = lane>>3:
    // A: row-half = m&1, k-half = m>>1 ; B: n-half = m>>1, k-half = m&1
    const int lm = lane >> 3, l7 = lane & 7;
    const int arow = l7 + (lm & 1) * 8,  acol = (lm >> 1) * 8;
    const int brow = l7 + (lm >> 1) * 8, bcol = (lm & 1) * 8;
    uint32_t aoff[4], boff[2];
#pragma unroll
    for (int mt = 0; mt < 4; mt++)
        aoff[mt] = ((wm + mt * 16 + arow) * HP2 + acol) * 2;
#pragma unroll
    for (int p = 0; p < 2; p++)
        boff[p] = ((wn + p * 16 + brow) * HP2 + bcol) * 2;

    float acc[4][4][4];
#pragma unroll
    for (int i = 0; i < 4; i++)
#pragma unroll
        for (int j = 0; j < 4; j++)
#pragma unroll
            for (int q = 0; q < 4; q++) acc[i][j][q] = 0.f;

    load_stage(Abase, Bbase, sa0, sb0, tid);
    asm volatile("cp.async.commit_group;\n");
    load_stage(Abase + 32, Bbase + 32, sa0 + saStride, sb0 + sbStride, tid);
    asm volatile("cp.async.commit_group;\n");

    const int NT = WDIM / 32;           // 32 iterations
    int s = 0;
    for (int kt = 0; kt < NT; kt++) {
        asm volatile("cp.async.wait_group 1;\n");
        __syncthreads();
        if (kt + 2 < NT) {
            int s2 = (s + 2 >= 3) ? s - 1 : s + 2;
            load_stage(Abase + (kt + 2) * 32, Bbase + (kt + 2) * 32,
                       sa0 + s2 * saStride, sb0 + s2 * sbStride, tid);
        }
        asm volatile("cp.async.commit_group;\n");

        const uint32_t sA = sa0 + s * saStride;
        const uint32_t sB = sb0 + s * sbStride;
#pragma unroll
        for (int ks = 0; ks < 2; ks++) {
            const uint32_t kb = ks * 32;           // 16 halves = 32 bytes
            uint32_t a[4][4], b[4][2];
#pragma unroll
            for (int mt = 0; mt < 4; mt++)
                LDSM4(a[mt][0], a[mt][1], a[mt][2], a[mt][3], sA + aoff[mt] + kb);
            LDSM4(b[0][0], b[0][1], b[1][0], b[1][1], sB + boff[0] + kb);
            LDSM4(b[2][0], b[2][1], b[3][0], b[3][1], sB + boff[1] + kb);
#pragma unroll
            for (int mt = 0; mt < 4; mt++)
#pragma unroll
                for (int nt = 0; nt < 4; nt++) {
                    asm volatile(
                        "mma.sync.aligned.m16n8k16.row.col.f32.f16.f16.f32 "
                        "{%0,%1,%2,%3}, {%4,%5,%6,%7}, {%8,%9}, {%0,%1,%2,%3};\n"
                        : "+f"(acc[mt][nt][0]), "+f"(acc[mt][nt][1]),
                          "+f"(acc[mt][nt][2]), "+f"(acc[mt][nt][3])
                        : "r"(a[mt][0]), "r"(a[mt][1]), "r"(a[mt][2]), "r"(a[mt][3]),
                          "r"(b[nt][0]), "r"(b[nt][1]));
                }
        }
        s = (s + 1 >= 3) ? 0 : s + 1;
    }

    if (SRC == 1) {
#pragma unroll
        for (int mt = 0; mt < 4; mt++) {
            int mrow = m0 + wm + mt * 16 + quad;
#pragma unroll
            for (int nt = 0; nt < 4; nt++) {
                int ncol = n0 + wn + nt * 8 + 2 * qid;
                float b0 = bias[ncol], b1 = bias[ncol + 1];
                *(half2*)(g_H2h + mrow * WDIM + ncol) =
                    __floats2half2_rn(gelu_f(acc[mt][nt][0] + b0),
                                      gelu_f(acc[mt][nt][1] + b1));
                *(half2*)(g_H2h + (mrow + 8) * WDIM + ncol) =
                    __floats2half2_rn(gelu_f(acc[mt][nt][2] + b0),
                                      gelu_f(acc[mt][nt][3] + b1));
            }
        }
    } else {
        float colacc[4][2];
#pragma unroll
        for (int nt = 0; nt < 4; nt++) { colacc[nt][0] = 0.f; colacc[nt][1] = 0.f; }
#pragma unroll
        for (int nt = 0; nt < 4; nt++) {
            int ncol = n0 + wn + nt * 8 + 2 * qid;
            float b0 = bias[ncol], b1 = bias[ncol + 1];
#pragma unroll
            for (int mt = 0; mt < 4; mt++) {
                colacc[nt][0] += gelu_f(acc[mt][nt][0] + b0) + gelu_f(acc[mt][nt][2] + b0);
                colacc[nt][1] += gelu_f(acc[mt][nt][1] + b1) + gelu_f(acc[mt][nt][3] + b1);
            }
        }
#pragma unroll
        for (int nt = 0; nt < 4; nt++)
#pragma unroll
            for (int c = 0; c < 2; c++) {
                float v = colacc[nt][c];
                v += __shfl_xor_sync(0xffffffffu, v, 4);
                v += __shfl_xor_sync(0xffffffffu, v, 8);
                v += __shfl_xor_sync(0xffffffffu, v, 16);
                colacc[nt][c] = v;
            }
        if (quad == 0) {
#pragma unroll
            for (int nt = 0; nt < 4; nt++) {
                int ncol = n0 + wn + nt * 8 + 2 * qid;
                atomicAdd(&g_HSUM[ncol], colacc[nt][0]);
                atomicAdd(&g_HSUM[ncol + 1], colacc[nt][1]);
            }
        }
    }
}

// ------ wsum GEMV: 2 rows per warp, 16 LDG.128 in flight (MLP x2) -----------
__global__ __launch_bounds__(256) void k_wsum(const float* __restrict__ W4,
                                              const float* __restrict__ b4, float Sf) {
    __shared__ float sh[WDIM];
    for (int i = threadIdx.x; i < WDIM; i += 256) sh[i] = g_HSUM[i];
    __syncthreads();
    int warp = threadIdx.x >> 5, lane = threadIdx.x & 31;
    int gw0 = (blockIdx.x * 8 + warp) * 2;            // rows gw0, gw0+1
    const float4* wr0 = (const float4*)(W4 + gw0 * WDIM);
    const float4* wr1 = (const float4*)(W4 + (gw0 + 1) * WDIM);
    float4 w[16];
#pragma unroll
    for (int it = 0; it < 8; it++) w[it] = wr0[lane + 32 * it];
#pragma unroll
    for (int it = 0; it < 8; it++) w[8 + it] = wr1[lane + 32 * it];
    float a0 = 0.f, a1 = 0.f;
#pragma unroll
    for (int it = 0; it < 8; it++) {
        const float* hp = sh + (lane + 32 * it) * 4;
        a0 += w[it].x * hp[0] + w[it].y * hp[1] + w[it].z * hp[2] + w[it].w * hp[3];
        a1 += w[8 + it].x * hp[0] + w[8 + it].y * hp[1] +
              w[8 + it].z * hp[2] + w[8 + it].w * hp[3];
    }
#pragma unroll
    for (int off = 16; off; off >>= 1) {
        a0 += __shfl_xor_sync(0xffffffffu, a0, off);
        a1 += __shfl_xor_sync(0xffffffffu, a1, off);
    }
    if (lane == 0) {
#pragma unroll
        for (int e = 0; e < 2; e++) {
            int gw = gw0 + e;
            float acc = e ? a1 : a0;
            int c = gw >> 10, ij = gw & 1023, i = ij >> 5, j = ij & 31;
            int row = 2 * i + ((c == 1 || c == 3) ? 1 : 0);
            int col = 2 * j + ((c == 1 || c == 2) ? 1 : 0);
            g_M[row * 64 + col] = acc + Sf * b4[gw];
        }
    }
}

// ---------------- Fourier evaluation (f32x2 packed math) --------------------
__global__ __launch_bounds__(128) void k_fourier(const float* __restrict__ r,
                                                 float* __restrict__ out, int NP) {
    __shared__ __align__(16) float sM[4096];
    for (int i = threadIdx.x; i < 4096; i += 128) sM[i] = g_M[i];
    __syncthreads();
    int n = blockIdx.x * 128 + threadIdx.x;
    if (n >= NP) return;
    float x = r[2 * n], y = r[2 * n + 1];
    const float w0 = 0.6283185307179586f;   // 2*pi/10
    float s1x, c1x, s1y, c1y;
    sincosf(w0 * x, &s1x, &c1x);
    sincosf(w0 * y, &s1y, &c1y);

    unsigned long long xd[64];
    xd[0] = pk2(c1x, c1x);
    xd[1] = pk2(s1x, s1x);
    float cc = c1x, ss = s1x;
#pragma unroll
    for (int i = 1; i < 32; i++) {
        float nc = cc * c1x - ss * s1x;
        float ns = ss * c1x + cc * s1x;
        xd[2 * i] = pk2(nc, nc);
        xd[2 * i + 1] = pk2(ns, ns);
        cc = nc; ss = ns;
    }

    uint32_t mbase = (uint32_t)__cvta_generic_to_shared(&sM[0]);
    unsigned long long acc2 = pk2(0.f, 0.f);
    float cy = c1y, sy = s1y;
#pragma unroll 1
    for (int jq = 0; jq < 16; jq++) {
        float cy2 = cy * c1y - sy * s1y;
        float sy2 = sy * c1y + cy * s1y;
        unsigned long long t01 = pk2(0.f, 0.f), t23 = pk2(0.f, 0.f);
        uint32_t addr = mbase + jq * 16;
#pragma unroll
        for (int i = 0; i < 64; i++) {
            unsigned long long m01, m23;
            asm("ld.shared.v2.b64 {%0,%1}, [%2];"
                : "=l"(m01), "=l"(m23) : "r"(addr + i * 256));
            fma2(t01, m01, xd[i]);
            fma2(t23, m23, xd[i]);
        }
        fma2(acc2, t01, pk2(cy, sy));
        fma2(acc2, t23, pk2(cy2, sy2));
        float cy3 = cy2 * c1y - sy2 * s1y;
        float sy3 = sy2 * c1y + cy2 * s1y;
        cy = cy3; sy = sy3;
    }
    float lo, hi;
    asm("mov.b64 {%0,%1}, %2;" : "=f"(lo), "=f"(hi) : "l"(acc2));
    out[n] = g_bsum + lo + hi;
}

// ---------------- launcher --------------------------------------------------
extern "C" void kernel_launch(void* const* d_in, const int* in_sizes, int n_in,
                              void* d_out, int out_size) {
    const float* sources = (const float*)d_in[0];
    const float* r       = (const float*)d_in[1];
    const float* W1      = (const float*)d_in[2];
    const float* b1      = (const float*)d_in[3];
    const float* W2      = (const float*)d_in[4];
    const float* b2      = (const float*)d_in[5];
    const float* W3      = (const float*)d_in[6];
    const float* b3      = (const float*)d_in[7];
    const float* W4      = (const float*)d_in[8];
    const float* b4      = (const float*)d_in[9];
    const float* Wb      = (const float*)d_in[10];
    const float* bb      = (const float*)d_in[11];
    float* out = (float*)d_out;

    int S  = in_sizes[0] / 4;          // 2048
    int NP = out_size;                 // 100000

    k_prep<<<9217, 256>>>(sources, W1, b1, W2, W3, Wb, bb, S);

    dim3 gg(WDIM / 64, SMAX / 128);    // (16, 16) = 256 CTAs
    k_gemm<1><<<gg, 128>>>(b2);
    k_gemm<2><<<gg, 128>>>(b3);

    k_wsum<<<256, 256>>>(W4, b4, (float)S);

    int nb = (NP + 127) / 128;
    k_fourier<<<nb, 128>>>(r, out, NP);
}

// round 17
// speedup vs baseline: 2.2056x; 1.3729x over previous
#include <cuda_runtime.h>
#include <cuda_fp16.h>
#include <math.h>
#include <stdint.h>

#define SMAX 2048
#define WDIM 1024

// ---------------- scratch (static device globals; no allocation) -------------
__device__ __half g_H1h[SMAX * WDIM];   // 4 MB
__device__ __half g_H2h[SMAX * WDIM];   // 4 MB
__device__ __half g_W2h[WDIM * WDIM];   // 2 MB
__device__ __half g_W3h[WDIM * WDIM];   // 2 MB
__device__ float g_HSUM[WDIM];
__device__ float g_M[64 * 64];
__device__ float g_bsum;

__device__ __forceinline__ float gelu_f(float x) {
    float t = tanhf(0.7978845608028654f * (x + 0.044715f * x * x * x));
    return 0.5f * x * (1.0f + t);
}

__device__ __forceinline__ void cp_async16(uint32_t dst, const void* src) {
    asm volatile("cp.async.cg.shared.global [%0], [%1], 16;\n" :: "r"(dst), "l"(src));
}

#define LDSM4(r0, r1, r2, r3, addr) \
    asm volatile("ldmatrix.sync.aligned.m8n8.x4.shared.b16 {%0,%1,%2,%3}, [%4];" \
                 : "=r"(r0), "=r"(r1), "=r"(r2), "=r"(r3) : "r"(addr))

// ---------- fused prep: W2/W3 -> fp16 | layer1 (4 out/thr) | bsum -----------
__global__ void k_prep(const float* __restrict__ src, const float* __restrict__ W1,
                       const float* __restrict__ b1, const float* __restrict__ W2,
                       const float* __restrict__ W3, const float* __restrict__ Wb,
                       const float* __restrict__ bb, int S) {
    int bid = blockIdx.x;
    int tid = threadIdx.x;
    if (bid < 1024) {                       // weights: 1M elems x2, 4 per thread
        int i4 = (bid * 256 + tid) * 4;
        float4 w2 = *(const float4*)(W2 + i4);
        float4 w3 = *(const float4*)(W3 + i4);
        __half2 a0 = __floats2half2_rn(w2.x, w2.y);
        __half2 a1 = __floats2half2_rn(w2.z, w2.w);
        __half2 b0 = __floats2half2_rn(w3.x, w3.y);
        __half2 b1h = __floats2half2_rn(w3.z, w3.w);
        *(uint2*)(g_W2h + i4) = make_uint2(*(uint32_t*)&a0, *(uint32_t*)&a1);
        *(uint2*)(g_W3h + i4) = make_uint2(*(uint32_t*)&b0, *(uint32_t*)&b1h);
    } else if (bid < 3072) {                // layer 1: 4 outputs per thread
        int idx4 = (bid - 1024) * 256 + tid;       // 0..524287
        int s = idx4 >> 8, o4 = (idx4 & 255) * 4;
        float4 sv = *(const float4*)(src + 4 * s);
        float4 bb4 = *(const float4*)(b1 + o4);
        float4 w0 = *(const float4*)(W1 + 4 * o4);
        float4 w1 = *(const float4*)(W1 + 4 * o4 + 4);
        float4 w2 = *(const float4*)(W1 + 4 * o4 + 8);
        float4 w3 = *(const float4*)(W1 + 4 * o4 + 12);
        float v0 = bb4.x + sv.x * w0.x + sv.y * w0.y + sv.z * w0.z + sv.w * w0.w;
        float v1 = bb4.y + sv.x * w1.x + sv.y * w1.y + sv.z * w1.z + sv.w * w1.w;
        float v2 = bb4.z + sv.x * w2.x + sv.y * w2.y + sv.z * w2.z + sv.w * w2.w;
        float v3 = bb4.w + sv.x * w3.x + sv.y * w3.y + sv.z * w3.z + sv.w * w3.w;
        __half2 h01 = __floats2half2_rn(gelu_f(v0), gelu_f(v1));
        __half2 h23 = __floats2half2_rn(gelu_f(v2), gelu_f(v3));
        *(uint2*)(g_H1h + s * WDIM + o4) = make_uint2(*(uint32_t*)&h01, *(uint32_t*)&h23);
    } else {                                // bias reduce + zero HSUM
        __shared__ float red[256];
        *(float4*)(g_HSUM + tid * 4) = make_float4(0.f, 0.f, 0.f, 0.f);
        float w0 = Wb[0], w1 = Wb[1], w2 = Wb[2], w3 = Wb[3];
        float acc = 0.f;
        for (int s = tid; s < S; s += 256) {
            float4 sv = *(const float4*)(src + 4 * s);
            acc += sv.x * w0 + sv.y * w1 + sv.z * w2 + sv.w * w3;
        }
        red[tid] = acc;
        __syncthreads();
        for (int off = 128; off > 0; off >>= 1) {
            if (tid < off) red[tid] += red[tid + off];
            __syncthreads();
        }
        if (tid == 0) g_bsum = red[0] + (float)S * bb[0];
    }
}

// ---------------- fp16 tensor-core GEMM: C = gelu(A @ B^T + bias) -----------
#define HP2 40

__device__ __forceinline__ void load_stage(const __half* __restrict__ Ab,
                                           const __half* __restrict__ Bb,
                                           uint32_t sa, uint32_t sb, int tid) {
#pragma unroll
    for (int i = 0; i < 4; i++) {
        int slot = tid + 128 * i, row = slot >> 2, h = slot & 3;
        cp_async16(sa + (row * HP2 + h * 8) * 2, Ab + row * WDIM + h * 8);
    }
#pragma unroll
    for (int i = 0; i < 2; i++) {
        int slot = tid + 128 * i, row = slot >> 2, h = slot & 3;
        cp_async16(sb + (row * HP2 + h * 8) * 2, Bb + row * WDIM + h * 8);
    }
}

template <int SRC>
__global__ __launch_bounds__(128) void k_gemm(const float* __restrict__ bias) {
    const __half* A = (SRC == 1) ? g_H1h : g_H2h;
    const __half* B = (SRC == 1) ? g_W2h : g_W3h;
    __shared__ __align__(16) __half As[3][128 * HP2];
    __shared__ __align__(16) __half Bs[3][64 * HP2];

    const int tid  = threadIdx.x;
    const int warp = tid >> 5, lane = tid & 31;
    const int quad = lane >> 2, qid = lane & 3;
    const int wm = (warp >> 1) * 64, wn = (warp & 1) * 32;
    const int m0 = blockIdx.y * 128, n0 = blockIdx.x * 64;

    const __half* Abase = A + m0 * WDIM;
    const __half* Bbase = B + n0 * WDIM;
    const uint32_t sa0 = (uint32_t)__cvta_generic_to_shared(&As[0][0]);
    const uint32_t sb0 = (uint32_t)__cvta_generic_to_shared(&Bs[0][0]);
    const uint32_t saStride = 128 * HP2 * 2, sbStride = 64 * HP2 * 2;

    const int lm = lane >> 3, l7 = lane & 7;
    const int arow = l7 + (lm & 1) * 8,  acol = (lm >> 1) * 8;
    const int brow = l7 + (lm >> 1) * 8, bcol = (lm & 1) * 8;
    uint32_t aoff[4], boff[2];
#pragma unroll
    for (int mt = 0; mt < 4; mt++)
        aoff[mt] = ((wm + mt * 16 + arow) * HP2 + acol) * 2;
#pragma unroll
    for (int p = 0; p < 2; p++)
        boff[p] = ((wn + p * 16 + brow) * HP2 + bcol) * 2;

    float acc[4][4][4];
#pragma unroll
    for (int i = 0; i < 4; i++)
#pragma unroll
        for (int j = 0; j < 4; j++)
#pragma unroll
            for (int q = 0; q < 4; q++) acc[i][j][q] = 0.f;

    load_stage(Abase, Bbase, sa0, sb0, tid);
    asm volatile("cp.async.commit_group;\n");
    load_stage(Abase + 32, Bbase + 32, sa0 + saStride, sb0 + sbStride, tid);
    asm volatile("cp.async.commit_group;\n");

    const int NT = WDIM / 32;
    int s = 0;
    for (int kt = 0; kt < NT; kt++) {
        asm volatile("cp.async.wait_group 1;\n");
        __syncthreads();
        if (kt + 2 < NT) {
            int s2 = (s + 2 >= 3) ? s - 1 : s + 2;
            load_stage(Abase + (kt + 2) * 32, Bbase + (kt + 2) * 32,
                       sa0 + s2 * saStride, sb0 + s2 * sbStride, tid);
        }
        asm volatile("cp.async.commit_group;\n");

        const uint32_t sA = sa0 + s * saStride;
        const uint32_t sB = sb0 + s * sbStride;
#pragma unroll
        for (int ks = 0; ks < 2; ks++) {
            const uint32_t kb = ks * 32;
            uint32_t a[4][4], b[4][2];
#pragma unroll
            for (int mt = 0; mt < 4; mt++)
                LDSM4(a[mt][0], a[mt][1], a[mt][2], a[mt][3], sA + aoff[mt] + kb);
            LDSM4(b[0][0], b[0][1], b[1][0], b[1][1], sB + boff[0] + kb);
            LDSM4(b[2][0], b[2][1], b[3][0], b[3][1], sB + boff[1] + kb);
#pragma unroll
            for (int mt = 0; mt < 4; mt++)
#pragma unroll
                for (int nt = 0; nt < 4; nt++) {
                    asm volatile(
                        "mma.sync.aligned.m16n8k16.row.col.f32.f16.f16.f32 "
                        "{%0,%1,%2,%3}, {%4,%5,%6,%7}, {%8,%9}, {%0,%1,%2,%3};\n"
                        : "+f"(acc[mt][nt][0]), "+f"(acc[mt][nt][1]),
                          "+f"(acc[mt][nt][2]), "+f"(acc[mt][nt][3])
                        : "r"(a[mt][0]), "r"(a[mt][1]), "r"(a[mt][2]), "r"(a[mt][3]),
                          "r"(b[nt][0]), "r"(b[nt][1]));
                }
        }
        s = (s + 1 >= 3) ? 0 : s + 1;
    }

    if (SRC == 1) {
#pragma unroll
        for (int mt = 0; mt < 4; mt++) {
            int mrow = m0 + wm + mt * 16 + quad;
#pragma unroll
            for (int nt = 0; nt < 4; nt++) {
                int ncol = n0 + wn + nt * 8 + 2 * qid;
                float b0 = bias[ncol], b1 = bias[ncol + 1];
                *(half2*)(g_H2h + mrow * WDIM + ncol) =
                    __floats2half2_rn(gelu_f(acc[mt][nt][0] + b0),
                                      gelu_f(acc[mt][nt][1] + b1));
                *(half2*)(g_H2h + (mrow + 8) * WDIM + ncol) =
                    __floats2half2_rn(gelu_f(acc[mt][nt][2] + b0),
                                      gelu_f(acc[mt][nt][3] + b1));
            }
        }
    } else {
        float colacc[4][2];
#pragma unroll
        for (int nt = 0; nt < 4; nt++) { colacc[nt][0] = 0.f; colacc[nt][1] = 0.f; }
#pragma unroll
        for (int nt = 0; nt < 4; nt++) {
            int ncol = n0 + wn + nt * 8 + 2 * qid;
            float b0 = bias[ncol], b1 = bias[ncol + 1];
#pragma unroll
            for (int mt = 0; mt < 4; mt++) {
                colacc[nt][0] += gelu_f(acc[mt][nt][0] + b0) + gelu_f(acc[mt][nt][2] + b0);
                colacc[nt][1] += gelu_f(acc[mt][nt][1] + b1) + gelu_f(acc[mt][nt][3] + b1);
            }
        }
#pragma unroll
        for (int nt = 0; nt < 4; nt++)
#pragma unroll
            for (int c = 0; c < 2; c++) {
                float v = colacc[nt][c];
                v += __shfl_xor_sync(0xffffffffu, v, 4);
                v += __shfl_xor_sync(0xffffffffu, v, 8);
                v += __shfl_xor_sync(0xffffffffu, v, 16);
                colacc[nt][c] = v;
            }
        if (quad == 0) {
#pragma unroll
            for (int nt = 0; nt < 4; nt++) {
                int ncol = n0 + wn + nt * 8 + 2 * qid;
                atomicAdd(&g_HSUM[ncol], colacc[nt][0]);
                atomicAdd(&g_HSUM[ncol + 1], colacc[nt][1]);
            }
        }
    }
}

// ---------------- wsum GEMV (round-8 form, best measured 7.46us) ------------
__global__ __launch_bounds__(256) void k_wsum(const float* __restrict__ W4,
                                              const float* __restrict__ b4, float Sf) {
    int gw = (blockIdx.x * 256 + threadIdx.x) >> 5;   // 0..4095
    int lane = threadIdx.x & 31;
    const float4* wr = (const float4*)(W4 + gw * WDIM);
    const float4* hs = (const float4*)g_HSUM;
    float acc = 0.f;
#pragma unroll
    for (int it = 0; it < 8; it++) {
        float4 w = wr[lane + 32 * it];
        float4 h = hs[lane + 32 * it];
        acc += w.x * h.x + w.y * h.y + w.z * h.z + w.w * h.w;
    }
#pragma unroll
    for (int off = 16; off; off >>= 1) acc += __shfl_xor_sync(0xffffffffu, acc, off);
    if (lane == 0) {
        int c = gw >> 10, ij = gw & 1023, i = ij >> 5, j = ij & 31;
        int row = 2 * i + ((c == 1 || c == 3) ? 1 : 0);
        int col = 2 * j + ((c == 1 || c == 2) ? 1 : 0);
        g_M[row * 64 + col] = acc + Sf * b4[gw];
    }
}

// ------------- Fourier via tensor cores: out_p = bsum + x_p^T M y_p ---------
// CTA = 128 points. Z(64x128) = M(64x64) @ Y^T via m16n8k16 (fp16 in, fp32 acc),
// then out_p = sum_i X[i][p] * Z[i][p] reduced over quads.
__global__ __launch_bounds__(128) void k_fourier(const float* __restrict__ r,
                                                 float* __restrict__ out, int NP) {
    __shared__ __align__(16) __half sM[64 * 72];    // 9.2 KB
    __shared__ __align__(16) __half sX[128 * 72];   // 18 KB
    __shared__ __align__(16) __half sY[128 * 72];   // 18 KB
    const int tid = threadIdx.x, warp = tid >> 5, lane = tid & 31;
    const int quad = lane >> 2, qid = lane & 3;
    const int n = blockIdx.x * 128 + tid;

    for (int i = tid; i < 4096; i += 128)
        sM[(i >> 6) * 72 + (i & 63)] = __float2half_rn(g_M[i]);

    float x = 0.f, y = 0.f;
    if (n < NP) { x = r[2 * n], y = r[2 * n + 1]; }
    const float w0 = 0.6283185307179586f;   // 2*pi/10
    float s1x, c1x, s1y, c1y;
    sincosf(w0 * x, &s1x, &c1x);
    sincosf(w0 * y, &s1y, &c1y);
    {
        float cx = c1x, sx = s1x, cy = c1y, sy = s1y;
        __half2* px = (__half2*)&sX[tid * 72];
        __half2* py = (__half2*)&sY[tid * 72];
        px[0] = __floats2half2_rn(cx, sx);
        py[0] = __floats2half2_rn(cy, sy);
#pragma unroll
        for (int i = 1; i < 32; i++) {
            float ncx = cx * c1x - sx * s1x;
            float nsx = sx * c1x + cx * s1x;
            float ncy = cy * c1y - sy * s1y;
            float nsy = sy * c1y + cy * s1y;
            px[i] = __floats2half2_rn(ncx, nsx);
            py[i] = __floats2half2_rn(ncy, nsy);
            cx = ncx; sx = nsx; cy = ncy; sy = nsy;
        }
    }
    __syncthreads();

    const int lm = lane >> 3, l7 = lane & 7;
    const int arow = l7 + (lm & 1) * 8,  acol = (lm >> 1) * 8;
    const int brow = l7 + (lm >> 1) * 8, bcol = (lm & 1) * 8;
    const uint32_t sMb = (uint32_t)__cvta_generic_to_shared(sM);
    const uint32_t sYb = (uint32_t)__cvta_generic_to_shared(sY);

    float acc[4][4][4];
#pragma unroll
    for (int i = 0; i < 4; i++)
#pragma unroll
        for (int j = 0; j < 4; j++)
#pragma unroll
            for (int q = 0; q < 4; q++) acc[i][j][q] = 0.f;

#pragma unroll
    for (int k = 0; k < 4; k++) {
        const int kb = k * 16;
        uint32_t a[4][4], b[4][2];
#pragma unroll
        for (int mt = 0; mt < 4; mt++)
            LDSM4(a[mt][0], a[mt][1], a[mt][2], a[mt][3],
                  sMb + ((mt * 16 + arow) * 72 + kb + acol) * 2);
        LDSM4(b[0][0], b[0][1], b[1][0], b[1][1],
              sYb + ((warp * 32 + brow) * 72 + kb + bcol) * 2);
        LDSM4(b[2][0], b[2][1], b[3][0], b[3][1],
              sYb + ((warp * 32 + 16 + brow) * 72 + kb + bcol) * 2);
#pragma unroll
        for (int mt = 0; mt < 4; mt++)
#pragma unroll
            for (int nt = 0; nt < 4; nt++) {
                asm volatile(
                    "mma.sync.aligned.m16n8k16.row.col.f32.f16.f16.f32 "
                    "{%0,%1,%2,%3}, {%4,%5,%6,%7}, {%8,%9}, {%0,%1,%2,%3};\n"
                    : "+f"(acc[mt][nt][0]), "+f"(acc[mt][nt][1]),
                      "+f"(acc[mt][nt][2]), "+f"(acc[mt][nt][3])
                    : "r"(a[mt][0]), "r"(a[mt][1]), "r"(a[mt][2]), "r"(a[mt][3]),
                      "r"(b[nt][0]), "r"(b[nt][1]));
            }
    }

    const float bsum = g_bsum;
#pragma unroll
    for (int nt = 0; nt < 4; nt++) {
        int p0 = warp * 32 + nt * 8 + 2 * qid;
        float s0 = 0.f, s1 = 0.f;
#pragma unroll
        for (int mt = 0; mt < 4; mt++) {
            float x0a = __half2float(sX[p0 * 72 + mt * 16 + quad]);
            float x0b = __half2float(sX[p0 * 72 + mt * 16 + quad + 8]);
            float x1a = __half2float(sX[(p0 + 1) * 72 + mt * 16 + quad]);
            float x1b = __half2float(sX[(p0 + 1) * 72 + mt * 16 + quad + 8]);
            s0 += x0a * acc[mt][nt][0] + x0b * acc[mt][nt][2];
            s1 += x1a * acc[mt][nt][1] + x1b * acc[mt][nt][3];
        }
#pragma unroll
        for (int off = 4; off < 32; off <<= 1) {
            s0 += __shfl_xor_sync(0xffffffffu, s0, off);
            s1 += __shfl_xor_sync(0xffffffffu, s1, off);
        }
        if (quad == 0) {
            int gp = blockIdx.x * 128 + p0;
            if (gp < NP) out[gp] = bsum + s0;
            if (gp + 1 < NP) out[gp + 1] = bsum + s1;
        }
    }
}

// ---------------- launcher --------------------------------------------------
extern "C" void kernel_launch(void* const* d_in, const int* in_sizes, int n_in,
                              void* d_out, int out_size) {
    const float* sources = (const float*)d_in[0];
    const float* r       = (const float*)d_in[1];
    const float* W1      = (const float*)d_in[2];
    const float* b1      = (const float*)d_in[3];
    const float* W2      = (const float*)d_in[4];
    const float* b2      = (const float*)d_in[5];
    const float* W3      = (const float*)d_in[6];
    const float* b3      = (const float*)d_in[7];
    const float* W4      = (const float*)d_in[8];
    const float* b4      = (const float*)d_in[9];
    const float* Wb      = (const float*)d_in[10];
    const float* bb      = (const float*)d_in[11];
    float* out = (float*)d_out;

    int S  = in_sizes[0] / 4;          // 2048
    int NP = out_size;                 // 100000

    k_prep<<<3073, 256>>>(sources, W1, b1, W2, W3, Wb, bb, S);

    dim3 gg(WDIM / 64, SMAX / 128);    // (16, 16) = 256 CTAs
    k_gemm<1><<<gg, 128>>>(b2);
    k_gemm<2><<<gg, 128>>>(b3);

    k_wsum<<<512, 256>>>(W4, b4, (float)S);

    int nb = (NP + 127) / 128;         // 782
    k_fourier<<<nb, 128>>>(r, out, NP);
}